// round 16
// baseline (speedup 1.0000x reference)
#include <cuda_runtime.h>
#include <cuda_bf16.h>
#include <math.h>
#include <cstdint>

#define BATCH 2
#define NSEQ  2048
#define DIM   2048
#define NH    16
#define DH    128
#define INNER 2048
#define KDIM  2048
#define QK_SCALE 0.08838834764831845f  /* 128^-0.5 */

// ---------------------------------------------------------------------------
// Scratch
// ---------------------------------------------------------------------------
__device__ float g_qproj[BATCH * NSEQ * INNER];
__device__ float g_kv[BATCH * NSEQ * 2 * DH];
__device__ float g_attn[BATCH * NSEQ * INNER];
__device__ float g_WT[(INNER + 2 * DH) * DIM];   // [Wq^T ; Wkv^T] 2304 x 2048
__device__ float g_WoutT[DIM * INNER];
// pre-split (bf16 hi/lo) rope outputs for flash
__device__ __nv_bfloat16 g_qs_h[BATCH * NSEQ * INNER];
__device__ __nv_bfloat16 g_qs_l[BATCH * NSEQ * INNER];
__device__ __nv_bfloat16 g_ks_h[BATCH * NSEQ * DH];
__device__ __nv_bfloat16 g_ks_l[BATCH * NSEQ * DH];
__device__ __nv_bfloat16 g_vs_h[BATCH * NSEQ * DH];
__device__ __nv_bfloat16 g_vs_l[BATCH * NSEQ * DH];

__device__ __forceinline__ uint32_t smem_u32(const void* p) {
    uint32_t a;
    asm("{ .reg .u64 t; cvta.to.shared.u64 t, %1; cvt.u32.u64 %0, t; }" : "=r"(a) : "l"(p));
    return a;
}
__device__ __forceinline__ void ldmat_x4(uint32_t* r, uint32_t addr) {
    asm volatile("ldmatrix.sync.aligned.m8n8.x4.shared.b16 {%0,%1,%2,%3}, [%4];"
                 : "=r"(r[0]), "=r"(r[1]), "=r"(r[2]), "=r"(r[3]) : "r"(addr));
}
__device__ __forceinline__ void ldmat_x4_t(uint32_t* r, uint32_t addr) {
    asm volatile("ldmatrix.sync.aligned.m8n8.x4.trans.shared.b16 {%0,%1,%2,%3}, [%4];"
                 : "=r"(r[0]), "=r"(r[1]), "=r"(r[2]), "=r"(r[3]) : "r"(addr));
}
__device__ __forceinline__ void mma_bf16(float* d, const uint32_t* a, const uint32_t* b) {
    asm("mma.sync.aligned.m16n8k16.row.col.f32.bf16.bf16.f32 "
        "{%0,%1,%2,%3}, {%4,%5,%6,%7}, {%8,%9}, {%0,%1,%2,%3};"
        : "+f"(d[0]), "+f"(d[1]), "+f"(d[2]), "+f"(d[3])
        : "r"(a[0]), "r"(a[1]), "r"(a[2]), "r"(a[3]), "r"(b[0]), "r"(b[1]));
}
__device__ __forceinline__ uint32_t pack_bf16x2(float x0, float x1) {
    uint32_t r;
    asm("cvt.rn.bf16x2.f32 %0, %1, %2;" : "=r"(r) : "f"(x1), "f"(x0));
    return r;
}
__device__ __forceinline__ void split_pair(float x0, float x1, uint32_t& hi, uint32_t& lo) {
    hi = pack_bf16x2(x0, x1);
    float h0 = __uint_as_float(hi << 16);
    float h1 = __uint_as_float(hi & 0xffff0000u);
    lo = pack_bf16x2(x0 - h0, x1 - h1);
}
__device__ __forceinline__ void split1(float x, __nv_bfloat16& hi, __nv_bfloat16& lo) {
    hi = __float2bfloat16_rn(x);
    lo = __float2bfloat16_rn(x - __bfloat162float(hi));
}

// ---------------------------------------------------------------------------
// Weight transpose: in [R, C] -> out [C, R]
// ---------------------------------------------------------------------------
__global__ void transpose_kernel(const float* __restrict__ in, float* __restrict__ out,
                                 int R, int C)
{
    __shared__ float t[32][33];
    int c0 = blockIdx.x << 5, r0 = blockIdx.y << 5;
    int x = threadIdx.x, y = threadIdx.y;
#pragma unroll
    for (int i = 0; i < 32; i += 8)
        t[y + i][x] = in[(size_t)(r0 + y + i) * C + c0 + x];
    __syncthreads();
#pragma unroll
    for (int i = 0; i < 32; i += 8)
        out[(size_t)(c0 + y + i) * R + r0 + x] = t[x][y + i];
}

// ---------------------------------------------------------------------------
// Split-bf16 mma.sync GEMM (R13): [C1 | C2] = A[M,2048] @ BT[*,2048]^T
// ---------------------------------------------------------------------------
#define PITCHB 80
#define BUF_BYTES (128 * PITCHB)
#define STAGE_BYTES (4 * BUF_BYTES)
#define GEMM_SMEM (2 * STAGE_BYTES)
#define NKIT (KDIM / 32)

extern __shared__ float fsm[];

__global__ __launch_bounds__(256, 1) void gemm_mma(
    const float* __restrict__ A, const float* __restrict__ BT,
    float* __restrict__ C1, float* __restrict__ C2,
    int M, int N1, int N2)
{
    char* sm = (char*)fsm;
    const uint32_t smb = smem_u32(sm);
    const int tid = threadIdx.x;
    const int wid = tid >> 5, L = tid & 31;
    const int wm = wid & 3, wn = wid >> 2;
    const int m0 = blockIdx.y << 7, n0 = blockIdx.x << 7;

    const int ldr = tid >> 3;
    const int ldc = tid & 7;

    float acc[2][8][4];
#pragma unroll
    for (int mi = 0; mi < 2; mi++)
#pragma unroll
        for (int ni = 0; ni < 8; ni++)
#pragma unroll
            for (int e = 0; e < 4; e++) acc[mi][ni][e] = 0.f;

    float4 va[4], vb[4];

    auto ldg_stage = [&](int kc) {
#pragma unroll
        for (int t = 0; t < 4; t++) {
            int r = ldr + (t << 5);
            va[t] = *(const float4*)&A[(size_t)(m0 + r) * KDIM + (kc << 5) + (ldc << 2)];
            vb[t] = *(const float4*)&BT[(size_t)(n0 + r) * KDIM + (kc << 5) + (ldc << 2)];
        }
    };
    auto sts_stage = [&](int stg) {
        char* base = sm + stg * STAGE_BYTES;
#pragma unroll
        for (int t = 0; t < 4; t++) {
            int r = ldr + (t << 5);
            uint32_t off = (uint32_t)r * PITCHB + (ldc << 3);
            uint32_t h0, l0, h1, l1;
            split_pair(va[t].x, va[t].y, h0, l0);
            split_pair(va[t].z, va[t].w, h1, l1);
            *(uint2*)(base + off)                 = make_uint2(h0, h1);
            *(uint2*)(base + BUF_BYTES + off)     = make_uint2(l0, l1);
            split_pair(vb[t].x, vb[t].y, h0, l0);
            split_pair(vb[t].z, vb[t].w, h1, l1);
            *(uint2*)(base + 2 * BUF_BYTES + off) = make_uint2(h0, h1);
            *(uint2*)(base + 3 * BUF_BYTES + off) = make_uint2(l0, l1);
        }
    };

    const uint32_t a_row_off = (uint32_t)(wm * 32 + (L & 15)) * PITCHB + ((L >> 4) << 4);
    const uint32_t b_row_off = (uint32_t)(wn * 64 + ((L >> 4) << 3) + (L & 7)) * PITCHB
                               + (((L >> 3) & 1) << 4);

    auto compute_stage = [&](int stg) {
        const uint32_t base = smb + stg * STAGE_BYTES;
#pragma unroll
        for (int ks = 0; ks < 2; ks++) {
            const uint32_t kso = (uint32_t)(ks << 5);
            uint32_t ah[2][4], al[2][4], bh[8][2], bl[8][2];
#pragma unroll
            for (int mi = 0; mi < 2; mi++) {
                uint32_t ad = base + a_row_off + (uint32_t)(mi * 16) * PITCHB + kso;
                ldmat_x4(ah[mi], ad);
                ldmat_x4(al[mi], ad + BUF_BYTES);
            }
#pragma unroll
            for (int nj = 0; nj < 4; nj++) {
                uint32_t bd = base + 2 * BUF_BYTES + b_row_off
                              + (uint32_t)(nj * 16) * PITCHB + kso;
                uint32_t r4[4];
                ldmat_x4(r4, bd);
                bh[2 * nj][0] = r4[0]; bh[2 * nj][1] = r4[1];
                bh[2 * nj + 1][0] = r4[2]; bh[2 * nj + 1][1] = r4[3];
                ldmat_x4(r4, bd + BUF_BYTES);
                bl[2 * nj][0] = r4[0]; bl[2 * nj][1] = r4[1];
                bl[2 * nj + 1][0] = r4[2]; bl[2 * nj + 1][1] = r4[3];
            }
#pragma unroll
            for (int mi = 0; mi < 2; mi++)
#pragma unroll
                for (int ni = 0; ni < 8; ni++)
                    mma_bf16(acc[mi][ni], ah[mi], bh[ni]);
#pragma unroll
            for (int mi = 0; mi < 2; mi++)
#pragma unroll
                for (int ni = 0; ni < 8; ni++)
                    mma_bf16(acc[mi][ni], ah[mi], bl[ni]);
#pragma unroll
            for (int mi = 0; mi < 2; mi++)
#pragma unroll
                for (int ni = 0; ni < 8; ni++)
                    mma_bf16(acc[mi][ni], al[mi], bh[ni]);
        }
    };

    ldg_stage(0);
    sts_stage(0);
    __syncthreads();
#pragma unroll 1
    for (int kc = 0; kc < NKIT; kc++) {
        if (kc + 1 < NKIT) ldg_stage(kc + 1);
        compute_stage(kc & 1);
        if (kc + 1 < NKIT) sts_stage((kc + 1) & 1);
        __syncthreads();
    }

    float* Cb;
    int cstride, cb0;
    if (n0 < N1) { Cb = C1; cstride = N1; cb0 = n0; }
    else         { Cb = C2; cstride = N2; cb0 = n0 - N1; }
#pragma unroll
    for (int mi = 0; mi < 2; mi++) {
        int row = m0 + wm * 32 + mi * 16 + (L >> 2);
#pragma unroll
        for (int ni = 0; ni < 8; ni++) {
            int col = cb0 + wn * 64 + ni * 8 + ((L & 3) << 1);
            *(float2*)&Cb[(size_t)row * cstride + col] =
                make_float2(acc[mi][ni][0], acc[mi][ni][1]);
            *(float2*)&Cb[(size_t)(row + 8) * cstride + col] =
                make_float2(acc[mi][ni][2], acc[mi][ni][3]);
        }
    }
}

// ---------------------------------------------------------------------------
// RoPE + split: q (rot+scale) -> g_qs, k (rot) -> g_ks, v (split) -> g_vs.
// unit 0..15 = q heads, 16 = k, 17 = v.
// ---------------------------------------------------------------------------
__global__ void rope_split_kernel()
{
    int t = blockIdx.x * blockDim.x + threadIdx.x;
    const int TOT = BATCH * NSEQ * 18 * 64;
    if (t >= TOT) return;
    int pair = t & 63;
    int unit = (t >> 6) % 18;
    int rest = t / (64 * 18);
    int n = rest % NSEQ;
    int b = rest / NSEQ;
    size_t bn = (size_t)(b * NSEQ + n);

    float y1, y2;
    __nv_bfloat16 *oh, *ol;
    size_t o1, o2;
    if (unit == 17) {                       // v: split only
        const float* base = g_kv + bn * 256 + 128;
        y1 = base[pair]; y2 = base[pair + 64];
        oh = g_vs_h; ol = g_vs_l;
        o1 = bn * DH + pair; o2 = o1 + 64;
    } else {
        float invf = powf(10000.f, -(float)(pair << 1) * (1.f / 128.f));
        float ang = (float)n * invf;
        float s, c;
        sincosf(ang, &s, &c);
        const float* base;
        float sc;
        if (unit < NH) {
            base = g_qproj + bn * INNER + unit * DH;
            sc = QK_SCALE;
            oh = g_qs_h; ol = g_qs_l;
            o1 = bn * INNER + unit * DH + pair; o2 = o1 + 64;
        } else {
            base = g_kv + bn * 256;
            sc = 1.f;
            oh = g_ks_h; ol = g_ks_l;
            o1 = bn * DH + pair; o2 = o1 + 64;
        }
        float x1 = base[pair], x2 = base[pair + 64];
        y1 = (x1 * c - x2 * s) * sc;
        y2 = (x2 * c + x1 * s) * sc;
    }
    __nv_bfloat16 hb, lb;
    split1(y1, hb, lb); oh[o1] = hb; ol[o1] = lb;
    split1(y2, hb, lb); oh[o2] = hb; ol[o2] = lb;
}

// ---------------------------------------------------------------------------
// Flash attention, split-bf16 mma, heaviest-first block order.
// R13 MMA structure (fully unrolled, compile-time indices); staging is pure
// uint4 copies from pre-split global buffers.
// SMEM (pitch 272B): [0] Qh [1] Ql [2] Kh [3] Kl [4] Vh [5] Vl
// ---------------------------------------------------------------------------
#define FB_PITCH 272
#define FB_SIZE (128 * FB_PITCH)
#define FLASH_SMEM (6 * FB_SIZE)

__global__ __launch_bounds__(256, 1) void flash_mma()
{
    char* sm = (char*)fsm;
    const uint32_t smb = smem_u32(sm);
    const int tid = threadIdx.x;
    const int wid = tid >> 5, L = tid & 31;
    const int ib = (int)gridDim.x - 1 - (int)blockIdx.x;   // heaviest first
    const int h = blockIdx.y, b = blockIdx.z;
    const int r0 = ib << 7;
    const int wr0 = wid << 4;

    const char* qhp = (const char*)(g_qs_h + (size_t)b * NSEQ * INNER + h * DH);
    const char* qlp = (const char*)(g_qs_l + (size_t)b * NSEQ * INNER + h * DH);
    const char* khp = (const char*)(g_ks_h + (size_t)b * NSEQ * DH);
    const char* klp = (const char*)(g_ks_l + (size_t)b * NSEQ * DH);
    const char* vhp = (const char*)(g_vs_h + (size_t)b * NSEQ * DH);
    const char* vlp = (const char*)(g_vs_l + (size_t)b * NSEQ * DH);

    // ---- stage Q (pre-split copies) ----
#pragma unroll
    for (int t = 0; t < 8; t++) {
        int idx = tid + (t << 8);
        int r = idx >> 4, c16 = (idx & 15) << 4;
        uint32_t off = (uint32_t)r * FB_PITCH + c16;
        size_t go = (size_t)(r0 + r) * (INNER * 2) + c16;
        *(uint4*)(sm + off)           = *(const uint4*)(qhp + go);
        *(uint4*)(sm + FB_SIZE + off) = *(const uint4*)(qlp + go);
    }

    const uint32_t aoff = (uint32_t)(wr0 + (L & 15)) * FB_PITCH + ((L >> 4) << 4);
    const uint32_t koff = (uint32_t)(((L >> 4) << 3) + (L & 7)) * FB_PITCH
                          + (((L >> 3) & 1) << 4);
    const uint32_t voff = (uint32_t)((((L >> 3) & 1) << 3) + (L & 7)) * FB_PITCH
                          + ((L >> 4) << 4);

    float sO[16][4];
    float m_i[2], l_i[2];
#pragma unroll
    for (int nj = 0; nj < 16; nj++)
#pragma unroll
        for (int e = 0; e < 4; e++) sO[nj][e] = 0.f;
    m_i[0] = m_i[1] = -INFINITY;
    l_i[0] = l_i[1] = 0.f;

#pragma unroll 1
    for (int jb = 0; jb <= ib; jb++) {
        __syncthreads();
        const int c0 = jb << 7;
        // ---- stage K/V (pre-split copies) ----
#pragma unroll
        for (int t = 0; t < 8; t++) {
            int idx = tid + (t << 8);
            int r = idx >> 4, c16 = (idx & 15) << 4;
            uint32_t off = (uint32_t)r * FB_PITCH + c16;
            size_t go = (size_t)(c0 + r) * (DH * 2) + c16;
            *(uint4*)(sm + 2 * FB_SIZE + off) = *(const uint4*)(khp + go);
            *(uint4*)(sm + 3 * FB_SIZE + off) = *(const uint4*)(klp + go);
            *(uint4*)(sm + 4 * FB_SIZE + off) = *(const uint4*)(vhp + go);
            *(uint4*)(sm + 5 * FB_SIZE + off) = *(const uint4*)(vlp + go);
        }
        __syncthreads();

        // ---- S = Q K^T (3-pass split MMAs) ----
        float s[16][4];
#pragma unroll
        for (int nj = 0; nj < 16; nj++)
#pragma unroll
            for (int e = 0; e < 4; e++) s[nj][e] = 0.f;
#pragma unroll
        for (int ks = 0; ks < 8; ks++) {
            const uint32_t kso = (uint32_t)(ks << 5);
            uint32_t ah[4], al[4];
            ldmat_x4(ah, smb + aoff + kso);
            ldmat_x4(al, smb + FB_SIZE + aoff + kso);
#pragma unroll
            for (int g = 0; g < 2; g++) {
                uint32_t bh[8][2], bl[8][2];
#pragma unroll
                for (int jj = 0; jj < 4; jj++) {
                    int njp = g * 4 + jj;
                    uint32_t kd = smb + 2 * FB_SIZE + koff
                                  + (uint32_t)(njp * 16) * FB_PITCH + kso;
                    uint32_t r4[4];
                    ldmat_x4(r4, kd);
                    bh[2 * jj][0] = r4[0]; bh[2 * jj][1] = r4[1];
                    bh[2 * jj + 1][0] = r4[2]; bh[2 * jj + 1][1] = r4[3];
                    ldmat_x4(r4, kd + FB_SIZE);
                    bl[2 * jj][0] = r4[0]; bl[2 * jj][1] = r4[1];
                    bl[2 * jj + 1][0] = r4[2]; bl[2 * jj + 1][1] = r4[3];
                }
#pragma unroll
                for (int t = 0; t < 8; t++) mma_bf16(s[8 * g + t], ah, bh[t]);
#pragma unroll
                for (int t = 0; t < 8; t++) mma_bf16(s[8 * g + t], ah, bl[t]);
#pragma unroll
                for (int t = 0; t < 8; t++) mma_bf16(s[8 * g + t], al, bh[t]);
            }
        }

        // ---- causal mask ----
        if (jb == ib) {
            int rr = L >> 2, cb = (L & 3) << 1;
#pragma unroll
            for (int nj = 0; nj < 16; nj++) {
                int col = nj * 8 + cb;
                int rA = wr0 + rr, rB = rA + 8;
                if (col     > rA) s[nj][0] = -1e30f;
                if (col + 1 > rA) s[nj][1] = -1e30f;
                if (col     > rB) s[nj][2] = -1e30f;
                if (col + 1 > rB) s[nj][3] = -1e30f;
            }
        }

        // ---- online softmax ----
#pragma unroll
        for (int h2 = 0; h2 < 2; h2++) {
            float mx = -INFINITY;
#pragma unroll
            for (int nj = 0; nj < 16; nj++) {
                mx = fmaxf(mx, s[nj][2 * h2]);
                mx = fmaxf(mx, s[nj][2 * h2 + 1]);
            }
            mx = fmaxf(mx, __shfl_xor_sync(0xffffffffu, mx, 1));
            mx = fmaxf(mx, __shfl_xor_sync(0xffffffffu, mx, 2));
            float mn = fmaxf(m_i[h2], mx);
            float alpha = __expf(m_i[h2] - mn);
            m_i[h2] = mn;
            float sum = 0.f;
#pragma unroll
            for (int nj = 0; nj < 16; nj++) {
                float p0 = __expf(s[nj][2 * h2] - mn);
                float p1 = __expf(s[nj][2 * h2 + 1] - mn);
                s[nj][2 * h2] = p0;
                s[nj][2 * h2 + 1] = p1;
                sum += p0 + p1;
            }
            sum += __shfl_xor_sync(0xffffffffu, sum, 1);
            sum += __shfl_xor_sync(0xffffffffu, sum, 2);
            l_i[h2] = l_i[h2] * alpha + sum;
#pragma unroll
            for (int nj = 0; nj < 16; nj++) {
                sO[nj][2 * h2] *= alpha;
                sO[nj][2 * h2 + 1] *= alpha;
            }
        }

        // ---- O += P @ V (3-pass split MMAs) ----
#pragma unroll
        for (int ks = 0; ks < 8; ks++) {
            uint32_t pah[4], pal[4];
            split_pair(s[2 * ks][0], s[2 * ks][1], pah[0], pal[0]);
            split_pair(s[2 * ks][2], s[2 * ks][3], pah[1], pal[1]);
            split_pair(s[2 * ks + 1][0], s[2 * ks + 1][1], pah[2], pal[2]);
            split_pair(s[2 * ks + 1][2], s[2 * ks + 1][3], pah[3], pal[3]);
#pragma unroll
            for (int g = 0; g < 2; g++) {
                uint32_t vh[8][2], vl[8][2];
#pragma unroll
                for (int jj = 0; jj < 4; jj++) {
                    int djp = g * 4 + jj;
                    uint32_t vaddr = smb + 4 * FB_SIZE + voff
                                     + (uint32_t)(ks * 16) * FB_PITCH
                                     + (uint32_t)(djp * 32);
                    uint32_t r4[4];
                    ldmat_x4_t(r4, vaddr);
                    vh[2 * jj][0] = r4[0]; vh[2 * jj][1] = r4[1];
                    vh[2 * jj + 1][0] = r4[2]; vh[2 * jj + 1][1] = r4[3];
                    ldmat_x4_t(r4, vaddr + FB_SIZE);
                    vl[2 * jj][0] = r4[0]; vl[2 * jj][1] = r4[1];
                    vl[2 * jj + 1][0] = r4[2]; vl[2 * jj + 1][1] = r4[3];
                }
#pragma unroll
                for (int t = 0; t < 8; t++) mma_bf16(sO[8 * g + t], pah, vh[t]);
#pragma unroll
                for (int t = 0; t < 8; t++) mma_bf16(sO[8 * g + t], pal, vh[t]);
#pragma unroll
                for (int t = 0; t < 8; t++) mma_bf16(sO[8 * g + t], pah, vl[t]);
            }
        }
    }

    float* og = g_attn + (size_t)b * NSEQ * INNER + h * DH;
    int rowa = r0 + wr0 + (L >> 2);
#pragma unroll
    for (int h2 = 0; h2 < 2; h2++) {
        float inv = 1.f / l_i[h2];
        float* orow = &og[(size_t)(rowa + 8 * h2) * INNER];
#pragma unroll
        for (int nj = 0; nj < 16; nj++) {
            int col = nj * 8 + ((L & 3) << 1);
            *(float2*)&orow[col] =
                make_float2(sO[nj][2 * h2] * inv, sO[nj][2 * h2 + 1] * inv);
        }
    }
}

// ---------------------------------------------------------------------------
extern "C" void kernel_launch(void* const* d_in, const int* in_sizes, int n_in,
                              void* d_out, int out_size)
{
    (void)in_sizes; (void)n_in; (void)out_size;
    const float* x    = (const float*)d_in[0];
    const float* Wq   = (const float*)d_in[1];
    const float* Wkv  = (const float*)d_in[2];
    const float* Wout = (const float*)d_in[3];
    float* out = (float*)d_out;

    void *pq, *pkv, *pattn, *pwt, *pwoutt;
    cudaGetSymbolAddress(&pq, g_qproj);
    cudaGetSymbolAddress(&pkv, g_kv);
    cudaGetSymbolAddress(&pattn, g_attn);
    cudaGetSymbolAddress(&pwt, g_WT);
    cudaGetSymbolAddress(&pwoutt, g_WoutT);

    cudaFuncSetAttribute(gemm_mma,
                         cudaFuncAttributeMaxDynamicSharedMemorySize, GEMM_SMEM);
    cudaFuncSetAttribute(flash_mma,
                         cudaFuncAttributeMaxDynamicSharedMemorySize, FLASH_SMEM);

    const int M = BATCH * NSEQ;       // 4096
    const int NTOT = INNER + 2 * DH;  // 2304
    dim3 tb(32, 8);

    // 0) transpose weights: Wq^T rows [0,2048), Wkv^T rows [2048,2304)
    transpose_kernel<<<dim3(INNER / 32, DIM / 32), tb>>>(Wq, (float*)pwt, DIM, INNER);
    transpose_kernel<<<dim3((2 * DH) / 32, DIM / 32), tb>>>(
        Wkv, (float*)pwt + (size_t)INNER * DIM, DIM, 2 * DH);
    transpose_kernel<<<dim3(DIM / 32, INNER / 32), tb>>>(Wout, (float*)pwoutt, INNER, DIM);

    // 1) fused [q | kv] = x @ [Wq | Wkv]
    gemm_mma<<<dim3(NTOT / 128, M / 128), 256, GEMM_SMEM>>>(
        x, (const float*)pwt, (float*)pq, (float*)pkv, M, INNER, 2 * DH);
    // 2) rope + pre-split q/k/v
    {
        int tot = BATCH * NSEQ * 18 * 64;
        rope_split_kernel<<<(tot + 255) / 256, 256>>>();
    }
    // 3) causal flash attention
    flash_mma<<<dim3(NSEQ / 128, NH, BATCH), 256, FLASH_SMEM>>>();
    // 4) out = attn @ Wout
    gemm_mma<<<dim3(DIM / 128, M / 128), 256, GEMM_SMEM>>>(
        (const float*)pattn, (const float*)pwoutt, out, out, M, DIM, DIM);
}

// round 17
// speedup vs baseline: 1.5638x; 1.5638x over previous
#include <cuda_runtime.h>
#include <cuda_bf16.h>
#include <math.h>
#include <cstdint>

#define BATCH 2
#define NSEQ  2048
#define DIM   2048
#define NH    16
#define DH    128
#define INNER 2048
#define KDIM  2048
#define QK_SCALE 0.08838834764831845f  /* 128^-0.5 */

// ---------------------------------------------------------------------------
// Scratch
// ---------------------------------------------------------------------------
__device__ float g_qproj[BATCH * NSEQ * INNER];
__device__ float g_kv[BATCH * NSEQ * 2 * DH];
__device__ float g_attn[BATCH * NSEQ * INNER];
__device__ float g_WT[(INNER + 2 * DH) * DIM];   // [Wq^T ; Wkv^T] 2304 x 2048
__device__ float g_WoutT[DIM * INNER];
// pre-split (bf16 hi/lo) rope outputs for flash
__device__ __nv_bfloat16 g_qs_h[BATCH * NSEQ * INNER];
__device__ __nv_bfloat16 g_qs_l[BATCH * NSEQ * INNER];
__device__ __nv_bfloat16 g_ks_h[BATCH * NSEQ * DH];
__device__ __nv_bfloat16 g_ks_l[BATCH * NSEQ * DH];
__device__ __nv_bfloat16 g_vs_h[BATCH * NSEQ * DH];
__device__ __nv_bfloat16 g_vs_l[BATCH * NSEQ * DH];

__device__ __forceinline__ uint32_t smem_u32(const void* p) {
    uint32_t a;
    asm("{ .reg .u64 t; cvta.to.shared.u64 t, %1; cvt.u32.u64 %0, t; }" : "=r"(a) : "l"(p));
    return a;
}
__device__ __forceinline__ void ldmat_x4(uint32_t* r, uint32_t addr) {
    asm volatile("ldmatrix.sync.aligned.m8n8.x4.shared.b16 {%0,%1,%2,%3}, [%4];"
                 : "=r"(r[0]), "=r"(r[1]), "=r"(r[2]), "=r"(r[3]) : "r"(addr));
}
__device__ __forceinline__ void ldmat_x4_t(uint32_t* r, uint32_t addr) {
    asm volatile("ldmatrix.sync.aligned.m8n8.x4.trans.shared.b16 {%0,%1,%2,%3}, [%4];"
                 : "=r"(r[0]), "=r"(r[1]), "=r"(r[2]), "=r"(r[3]) : "r"(addr));
}
__device__ __forceinline__ void mma_bf16(float* d, const uint32_t* a, const uint32_t* b) {
    asm("mma.sync.aligned.m16n8k16.row.col.f32.bf16.bf16.f32 "
        "{%0,%1,%2,%3}, {%4,%5,%6,%7}, {%8,%9}, {%0,%1,%2,%3};"
        : "+f"(d[0]), "+f"(d[1]), "+f"(d[2]), "+f"(d[3])
        : "r"(a[0]), "r"(a[1]), "r"(a[2]), "r"(a[3]), "r"(b[0]), "r"(b[1]));
}
__device__ __forceinline__ uint32_t pack_bf16x2(float x0, float x1) {
    uint32_t r;
    asm("cvt.rn.bf16x2.f32 %0, %1, %2;" : "=r"(r) : "f"(x1), "f"(x0));
    return r;
}
__device__ __forceinline__ void split_pair(float x0, float x1, uint32_t& hi, uint32_t& lo) {
    hi = pack_bf16x2(x0, x1);
    float h0 = __uint_as_float(hi << 16);
    float h1 = __uint_as_float(hi & 0xffff0000u);
    lo = pack_bf16x2(x0 - h0, x1 - h1);
}
__device__ __forceinline__ void split1(float x, __nv_bfloat16& hi, __nv_bfloat16& lo) {
    hi = __float2bfloat16_rn(x);
    lo = __float2bfloat16_rn(x - __bfloat162float(hi));
}

// ---------------------------------------------------------------------------
// Weight transpose: in [R, C] -> out [C, R]
// ---------------------------------------------------------------------------
__global__ void transpose_kernel(const float* __restrict__ in, float* __restrict__ out,
                                 int R, int C)
{
    __shared__ float t[32][33];
    int c0 = blockIdx.x << 5, r0 = blockIdx.y << 5;
    int x = threadIdx.x, y = threadIdx.y;
#pragma unroll
    for (int i = 0; i < 32; i += 8)
        t[y + i][x] = in[(size_t)(r0 + y + i) * C + c0 + x];
    __syncthreads();
#pragma unroll
    for (int i = 0; i < 32; i += 8)
        out[(size_t)(c0 + y + i) * R + r0 + x] = t[x][y + i];
}

// ---------------------------------------------------------------------------
// Split-bf16 mma.sync GEMM (R13): [C1 | C2] = A[M,2048] @ BT[*,2048]^T
// ---------------------------------------------------------------------------
#define PITCHB 80
#define BUF_BYTES (128 * PITCHB)
#define STAGE_BYTES (4 * BUF_BYTES)
#define GEMM_SMEM (2 * STAGE_BYTES)
#define NKIT (KDIM / 32)

extern __shared__ float fsm[];

__global__ __launch_bounds__(256, 1) void gemm_mma(
    const float* __restrict__ A, const float* __restrict__ BT,
    float* __restrict__ C1, float* __restrict__ C2,
    int M, int N1, int N2)
{
    char* sm = (char*)fsm;
    const uint32_t smb = smem_u32(sm);
    const int tid = threadIdx.x;
    const int wid = tid >> 5, L = tid & 31;
    const int wm = wid & 3, wn = wid >> 2;
    const int m0 = blockIdx.y << 7, n0 = blockIdx.x << 7;

    const int ldr = tid >> 3;
    const int ldc = tid & 7;

    float acc[2][8][4];
#pragma unroll
    for (int mi = 0; mi < 2; mi++)
#pragma unroll
        for (int ni = 0; ni < 8; ni++)
#pragma unroll
            for (int e = 0; e < 4; e++) acc[mi][ni][e] = 0.f;

    float4 va[4], vb[4];

    auto ldg_stage = [&](int kc) {
#pragma unroll
        for (int t = 0; t < 4; t++) {
            int r = ldr + (t << 5);
            va[t] = *(const float4*)&A[(size_t)(m0 + r) * KDIM + (kc << 5) + (ldc << 2)];
            vb[t] = *(const float4*)&BT[(size_t)(n0 + r) * KDIM + (kc << 5) + (ldc << 2)];
        }
    };
    auto sts_stage = [&](int stg) {
        char* base = sm + stg * STAGE_BYTES;
#pragma unroll
        for (int t = 0; t < 4; t++) {
            int r = ldr + (t << 5);
            uint32_t off = (uint32_t)r * PITCHB + (ldc << 3);
            uint32_t h0, l0, h1, l1;
            split_pair(va[t].x, va[t].y, h0, l0);
            split_pair(va[t].z, va[t].w, h1, l1);
            *(uint2*)(base + off)                 = make_uint2(h0, h1);
            *(uint2*)(base + BUF_BYTES + off)     = make_uint2(l0, l1);
            split_pair(vb[t].x, vb[t].y, h0, l0);
            split_pair(vb[t].z, vb[t].w, h1, l1);
            *(uint2*)(base + 2 * BUF_BYTES + off) = make_uint2(h0, h1);
            *(uint2*)(base + 3 * BUF_BYTES + off) = make_uint2(l0, l1);
        }
    };

    const uint32_t a_row_off = (uint32_t)(wm * 32 + (L & 15)) * PITCHB + ((L >> 4) << 4);
    const uint32_t b_row_off = (uint32_t)(wn * 64 + ((L >> 4) << 3) + (L & 7)) * PITCHB
                               + (((L >> 3) & 1) << 4);

    auto compute_stage = [&](int stg) {
        const uint32_t base = smb + stg * STAGE_BYTES;
#pragma unroll
        for (int ks = 0; ks < 2; ks++) {
            const uint32_t kso = (uint32_t)(ks << 5);
            uint32_t ah[2][4], al[2][4], bh[8][2], bl[8][2];
#pragma unroll
            for (int mi = 0; mi < 2; mi++) {
                uint32_t ad = base + a_row_off + (uint32_t)(mi * 16) * PITCHB + kso;
                ldmat_x4(ah[mi], ad);
                ldmat_x4(al[mi], ad + BUF_BYTES);
            }
#pragma unroll
            for (int nj = 0; nj < 4; nj++) {
                uint32_t bd = base + 2 * BUF_BYTES + b_row_off
                              + (uint32_t)(nj * 16) * PITCHB + kso;
                uint32_t r4[4];
                ldmat_x4(r4, bd);
                bh[2 * nj][0] = r4[0]; bh[2 * nj][1] = r4[1];
                bh[2 * nj + 1][0] = r4[2]; bh[2 * nj + 1][1] = r4[3];
                ldmat_x4(r4, bd + BUF_BYTES);
                bl[2 * nj][0] = r4[0]; bl[2 * nj][1] = r4[1];
                bl[2 * nj + 1][0] = r4[2]; bl[2 * nj + 1][1] = r4[3];
            }
#pragma unroll
            for (int mi = 0; mi < 2; mi++)
#pragma unroll
                for (int ni = 0; ni < 8; ni++)
                    mma_bf16(acc[mi][ni], ah[mi], bh[ni]);
#pragma unroll
            for (int mi = 0; mi < 2; mi++)
#pragma unroll
                for (int ni = 0; ni < 8; ni++)
                    mma_bf16(acc[mi][ni], ah[mi], bl[ni]);
#pragma unroll
            for (int mi = 0; mi < 2; mi++)
#pragma unroll
                for (int ni = 0; ni < 8; ni++)
                    mma_bf16(acc[mi][ni], al[mi], bh[ni]);
        }
    };

    ldg_stage(0);
    sts_stage(0);
    __syncthreads();
#pragma unroll 1
    for (int kc = 0; kc < NKIT; kc++) {
        if (kc + 1 < NKIT) ldg_stage(kc + 1);
        compute_stage(kc & 1);
        if (kc + 1 < NKIT) sts_stage((kc + 1) & 1);
        __syncthreads();
    }

    float* Cb;
    int cstride, cb0;
    if (n0 < N1) { Cb = C1; cstride = N1; cb0 = n0; }
    else         { Cb = C2; cstride = N2; cb0 = n0 - N1; }
#pragma unroll
    for (int mi = 0; mi < 2; mi++) {
        int row = m0 + wm * 32 + mi * 16 + (L >> 2);
#pragma unroll
        for (int ni = 0; ni < 8; ni++) {
            int col = cb0 + wn * 64 + ni * 8 + ((L & 3) << 1);
            *(float2*)&Cb[(size_t)row * cstride + col] =
                make_float2(acc[mi][ni][0], acc[mi][ni][1]);
            *(float2*)&Cb[(size_t)(row + 8) * cstride + col] =
                make_float2(acc[mi][ni][2], acc[mi][ni][3]);
        }
    }
}

// ---------------------------------------------------------------------------
// RoPE + split: q (rot+scale) -> g_qs, k (rot) -> g_ks, v (split) -> g_vs.
// unit 0..15 = q heads, 16 = k, 17 = v.
// ---------------------------------------------------------------------------
__global__ void rope_split_kernel()
{
    int t = blockIdx.x * blockDim.x + threadIdx.x;
    const int TOT = BATCH * NSEQ * 18 * 64;
    if (t >= TOT) return;
    int pair = t & 63;
    int unit = (t >> 6) % 18;
    int rest = t / (64 * 18);
    int n = rest % NSEQ;
    int b = rest / NSEQ;
    size_t bn = (size_t)(b * NSEQ + n);

    float y1, y2;
    __nv_bfloat16 *oh, *ol;
    size_t o1, o2;
    if (unit == 17) {                       // v: split only
        const float* base = g_kv + bn * 256 + 128;
        y1 = base[pair]; y2 = base[pair + 64];
        oh = g_vs_h; ol = g_vs_l;
        o1 = bn * DH + pair; o2 = o1 + 64;
    } else {
        float invf = powf(10000.f, -(float)(pair << 1) * (1.f / 128.f));
        float ang = (float)n * invf;
        float s, c;
        sincosf(ang, &s, &c);
        const float* base;
        float sc;
        if (unit < NH) {
            base = g_qproj + bn * INNER + unit * DH;
            sc = QK_SCALE;
            oh = g_qs_h; ol = g_qs_l;
            o1 = bn * INNER + unit * DH + pair; o2 = o1 + 64;
        } else {
            base = g_kv + bn * 256;
            sc = 1.f;
            oh = g_ks_h; ol = g_ks_l;
            o1 = bn * DH + pair; o2 = o1 + 64;
        }
        float x1 = base[pair], x2 = base[pair + 64];
        y1 = (x1 * c - x2 * s) * sc;
        y2 = (x2 * c + x1 * s) * sc;
    }
    __nv_bfloat16 hb, lb;
    split1(y1, hb, lb); oh[o1] = hb; ol[o1] = lb;
    split1(y2, hb, lb); oh[o2] = hb; ol[o2] = lb;
}

// ---------------------------------------------------------------------------
// Flash attention, split-bf16 mma, heaviest-first block order.
// R13 MMA structure (fully unrolled, compile-time indices); staging is pure
// uint4 copies from pre-split global buffers.
// SMEM (pitch 272B): [0] Qh [1] Ql [2] Kh [3] Kl [4] Vh [5] Vl
// ---------------------------------------------------------------------------
#define FB_PITCH 272
#define FB_SIZE (128 * FB_PITCH)
#define FLASH_SMEM (6 * FB_SIZE)

__global__ __launch_bounds__(256, 1) void flash_mma()
{
    char* sm = (char*)fsm;
    const uint32_t smb = smem_u32(sm);
    const int tid = threadIdx.x;
    const int wid = tid >> 5, L = tid & 31;
    const int ib = (int)gridDim.x - 1 - (int)blockIdx.x;   // heaviest first
    const int h = blockIdx.y, b = blockIdx.z;
    const int r0 = ib << 7;
    const int wr0 = wid << 4;

    const char* qhp = (const char*)(g_qs_h + (size_t)b * NSEQ * INNER + h * DH);
    const char* qlp = (const char*)(g_qs_l + (size_t)b * NSEQ * INNER + h * DH);
    const char* khp = (const char*)(g_ks_h + (size_t)b * NSEQ * DH);
    const char* klp = (const char*)(g_ks_l + (size_t)b * NSEQ * DH);
    const char* vhp = (const char*)(g_vs_h + (size_t)b * NSEQ * DH);
    const char* vlp = (const char*)(g_vs_l + (size_t)b * NSEQ * DH);

    // ---- stage Q (pre-split copies) ----
#pragma unroll
    for (int t = 0; t < 8; t++) {
        int idx = tid + (t << 8);
        int r = idx >> 4, c16 = (idx & 15) << 4;
        uint32_t off = (uint32_t)r * FB_PITCH + c16;
        size_t go = (size_t)(r0 + r) * (INNER * 2) + c16;
        *(uint4*)(sm + off)           = *(const uint4*)(qhp + go);
        *(uint4*)(sm + FB_SIZE + off) = *(const uint4*)(qlp + go);
    }

    const uint32_t aoff = (uint32_t)(wr0 + (L & 15)) * FB_PITCH + ((L >> 4) << 4);
    const uint32_t koff = (uint32_t)(((L >> 4) << 3) + (L & 7)) * FB_PITCH
                          + (((L >> 3) & 1) << 4);
    const uint32_t voff = (uint32_t)((((L >> 3) & 1) << 3) + (L & 7)) * FB_PITCH
                          + ((L >> 4) << 4);

    float sO[16][4];
    float m_i[2], l_i[2];
#pragma unroll
    for (int nj = 0; nj < 16; nj++)
#pragma unroll
        for (int e = 0; e < 4; e++) sO[nj][e] = 0.f;
    m_i[0] = m_i[1] = -INFINITY;
    l_i[0] = l_i[1] = 0.f;

#pragma unroll 1
    for (int jb = 0; jb <= ib; jb++) {
        __syncthreads();
        const int c0 = jb << 7;
        // ---- stage K/V (pre-split copies) ----
#pragma unroll
        for (int t = 0; t < 8; t++) {
            int idx = tid + (t << 8);
            int r = idx >> 4, c16 = (idx & 15) << 4;
            uint32_t off = (uint32_t)r * FB_PITCH + c16;
            size_t go = (size_t)(c0 + r) * (DH * 2) + c16;
            *(uint4*)(sm + 2 * FB_SIZE + off) = *(const uint4*)(khp + go);
            *(uint4*)(sm + 3 * FB_SIZE + off) = *(const uint4*)(klp + go);
            *(uint4*)(sm + 4 * FB_SIZE + off) = *(const uint4*)(vhp + go);
            *(uint4*)(sm + 5 * FB_SIZE + off) = *(const uint4*)(vlp + go);
        }
        __syncthreads();

        // ---- S = Q K^T (3-pass split MMAs) ----
        float s[16][4];
#pragma unroll
        for (int nj = 0; nj < 16; nj++)
#pragma unroll
            for (int e = 0; e < 4; e++) s[nj][e] = 0.f;
#pragma unroll
        for (int ks = 0; ks < 8; ks++) {
            const uint32_t kso = (uint32_t)(ks << 5);
            uint32_t ah[4], al[4];
            ldmat_x4(ah, smb + aoff + kso);
            ldmat_x4(al, smb + FB_SIZE + aoff + kso);
#pragma unroll
            for (int g = 0; g < 2; g++) {
                uint32_t bh[8][2], bl[8][2];
#pragma unroll
                for (int jj = 0; jj < 4; jj++) {
                    int njp = g * 4 + jj;
                    uint32_t kd = smb + 2 * FB_SIZE + koff
                                  + (uint32_t)(njp * 16) * FB_PITCH + kso;
                    uint32_t r4[4];
                    ldmat_x4(r4, kd);
                    bh[2 * jj][0] = r4[0]; bh[2 * jj][1] = r4[1];
                    bh[2 * jj + 1][0] = r4[2]; bh[2 * jj + 1][1] = r4[3];
                    ldmat_x4(r4, kd + FB_SIZE);
                    bl[2 * jj][0] = r4[0]; bl[2 * jj][1] = r4[1];
                    bl[2 * jj + 1][0] = r4[2]; bl[2 * jj + 1][1] = r4[3];
                }
#pragma unroll
                for (int t = 0; t < 8; t++) mma_bf16(s[8 * g + t], ah, bh[t]);
#pragma unroll
                for (int t = 0; t < 8; t++) mma_bf16(s[8 * g + t], ah, bl[t]);
#pragma unroll
                for (int t = 0; t < 8; t++) mma_bf16(s[8 * g + t], al, bh[t]);
            }
        }

        // ---- causal mask ----
        if (jb == ib) {
            int rr = L >> 2, cb = (L & 3) << 1;
#pragma unroll
            for (int nj = 0; nj < 16; nj++) {
                int col = nj * 8 + cb;
                int rA = wr0 + rr, rB = rA + 8;
                if (col     > rA) s[nj][0] = -1e30f;
                if (col + 1 > rA) s[nj][1] = -1e30f;
                if (col     > rB) s[nj][2] = -1e30f;
                if (col + 1 > rB) s[nj][3] = -1e30f;
            }
        }

        // ---- online softmax ----
#pragma unroll
        for (int h2 = 0; h2 < 2; h2++) {
            float mx = -INFINITY;
#pragma unroll
            for (int nj = 0; nj < 16; nj++) {
                mx = fmaxf(mx, s[nj][2 * h2]);
                mx = fmaxf(mx, s[nj][2 * h2 + 1]);
            }
            mx = fmaxf(mx, __shfl_xor_sync(0xffffffffu, mx, 1));
            mx = fmaxf(mx, __shfl_xor_sync(0xffffffffu, mx, 2));
            float mn = fmaxf(m_i[h2], mx);
            float alpha = __expf(m_i[h2] - mn);
            m_i[h2] = mn;
            float sum = 0.f;
#pragma unroll
            for (int nj = 0; nj < 16; nj++) {
                float p0 = __expf(s[nj][2 * h2] - mn);
                float p1 = __expf(s[nj][2 * h2 + 1] - mn);
                s[nj][2 * h2] = p0;
                s[nj][2 * h2 + 1] = p1;
                sum += p0 + p1;
            }
            sum += __shfl_xor_sync(0xffffffffu, sum, 1);
            sum += __shfl_xor_sync(0xffffffffu, sum, 2);
            l_i[h2] = l_i[h2] * alpha + sum;
#pragma unroll
            for (int nj = 0; nj < 16; nj++) {
                sO[nj][2 * h2] *= alpha;
                sO[nj][2 * h2 + 1] *= alpha;
            }
        }

        // ---- O += P @ V (3-pass split MMAs) ----
#pragma unroll
        for (int ks = 0; ks < 8; ks++) {
            uint32_t pah[4], pal[4];
            split_pair(s[2 * ks][0], s[2 * ks][1], pah[0], pal[0]);
            split_pair(s[2 * ks][2], s[2 * ks][3], pah[1], pal[1]);
            split_pair(s[2 * ks + 1][0], s[2 * ks + 1][1], pah[2], pal[2]);
            split_pair(s[2 * ks + 1][2], s[2 * ks + 1][3], pah[3], pal[3]);
#pragma unroll
            for (int g = 0; g < 2; g++) {
                uint32_t vh[8][2], vl[8][2];
#pragma unroll
                for (int jj = 0; jj < 4; jj++) {
                    int djp = g * 4 + jj;
                    uint32_t vaddr = smb + 4 * FB_SIZE + voff
                                     + (uint32_t)(ks * 16) * FB_PITCH
                                     + (uint32_t)(djp * 32);
                    uint32_t r4[4];
                    ldmat_x4_t(r4, vaddr);
                    vh[2 * jj][0] = r4[0]; vh[2 * jj][1] = r4[1];
                    vh[2 * jj + 1][0] = r4[2]; vh[2 * jj + 1][1] = r4[3];
                    ldmat_x4_t(r4, vaddr + FB_SIZE);
                    vl[2 * jj][0] = r4[0]; vl[2 * jj][1] = r4[1];
                    vl[2 * jj + 1][0] = r4[2]; vl[2 * jj + 1][1] = r4[3];
                }
#pragma unroll
                for (int t = 0; t < 8; t++) mma_bf16(sO[8 * g + t], pah, vh[t]);
#pragma unroll
                for (int t = 0; t < 8; t++) mma_bf16(sO[8 * g + t], pal, vh[t]);
#pragma unroll
                for (int t = 0; t < 8; t++) mma_bf16(sO[8 * g + t], pah, vl[t]);
            }
        }
    }

    float* og = g_attn + (size_t)b * NSEQ * INNER + h * DH;
    int rowa = r0 + wr0 + (L >> 2);
#pragma unroll
    for (int h2 = 0; h2 < 2; h2++) {
        float inv = 1.f / l_i[h2];
        float* orow = &og[(size_t)(rowa + 8 * h2) * INNER];
#pragma unroll
        for (int nj = 0; nj < 16; nj++) {
            int col = nj * 8 + ((L & 3) << 1);
            *(float2*)&orow[col] =
                make_float2(sO[nj][2 * h2] * inv, sO[nj][2 * h2 + 1] * inv);
        }
    }
}

// ---------------------------------------------------------------------------
extern "C" void kernel_launch(void* const* d_in, const int* in_sizes, int n_in,
                              void* d_out, int out_size)
{
    (void)in_sizes; (void)n_in; (void)out_size;
    const float* x    = (const float*)d_in[0];
    const float* Wq   = (const float*)d_in[1];
    const float* Wkv  = (const float*)d_in[2];
    const float* Wout = (const float*)d_in[3];
    float* out = (float*)d_out;

    void *pq, *pkv, *pattn, *pwt, *pwoutt;
    cudaGetSymbolAddress(&pq, g_qproj);
    cudaGetSymbolAddress(&pkv, g_kv);
    cudaGetSymbolAddress(&pattn, g_attn);
    cudaGetSymbolAddress(&pwt, g_WT);
    cudaGetSymbolAddress(&pwoutt, g_WoutT);

    cudaFuncSetAttribute(gemm_mma,
                         cudaFuncAttributeMaxDynamicSharedMemorySize, GEMM_SMEM);
    cudaFuncSetAttribute(flash_mma,
                         cudaFuncAttributeMaxDynamicSharedMemorySize, FLASH_SMEM);

    const int M = BATCH * NSEQ;       // 4096
    const int NTOT = INNER + 2 * DH;  // 2304
    dim3 tb(32, 8);

    // 0) transpose weights: Wq^T rows [0,2048), Wkv^T rows [2048,2304)
    transpose_kernel<<<dim3(INNER / 32, DIM / 32), tb>>>(Wq, (float*)pwt, DIM, INNER);
    transpose_kernel<<<dim3((2 * DH) / 32, DIM / 32), tb>>>(
        Wkv, (float*)pwt + (size_t)INNER * DIM, DIM, 2 * DH);
    transpose_kernel<<<dim3(DIM / 32, INNER / 32), tb>>>(Wout, (float*)pwoutt, INNER, DIM);

    // 1) fused [q | kv] = x @ [Wq | Wkv]
    gemm_mma<<<dim3(NTOT / 128, M / 128), 256, GEMM_SMEM>>>(
        x, (const float*)pwt, (float*)pq, (float*)pkv, M, INNER, 2 * DH);
    // 2) rope + pre-split q/k/v
    {
        int tot = BATCH * NSEQ * 18 * 64;
        rope_split_kernel<<<(tot + 255) / 256, 256>>>();
    }
    // 3) causal flash attention
    flash_mma<<<dim3(NSEQ / 128, NH, BATCH), 256, FLASH_SMEM>>>();
    // 4) out = attn @ Wout
    gemm_mma<<<dim3(DIM / 128, M / 128), 256, GEMM_SMEM>>>(
        (const float*)pattn, (const float*)pwoutt, out, out, M, DIM, DIM);
}